// round 15
// baseline (speedup 1.0000x reference)
#include <cuda_runtime.h>
#include <cuda_bf16.h>
#include <cstdint>

// Embedding gather via bulk-DMA: out[s,:] = weights[x[s],:]
// x: [8192] int32, weights: [49408, 768] fp32, out: [8192, 768] fp32
//
// Converged design (R5 geometry, best profiled+timed): 1 driver thread/CTA,
// 8 rows of 3072 B in flight via cp.async.bulk, grid=1024.
// Overhead strip vs R5:
//  - no per-iteration proxy fences (async->async ordering comes from the
//    mbarrier wait; only the post-init fence is required)
//  - all 8 index loads hoisted ahead of the issue loop
//  - one commit_group for all 8 stores

#define SEQ       8192
#define ROW_BYTES 3072
#define RPC       8            // rows per CTA
#define GRID      (SEQ / RPC)  // 1024

__device__ __forceinline__ uint32_t smem_u32(const void* p) {
    uint32_t a;
    asm("{ .reg .u64 t; cvta.to.shared.u64 t, %1; cvt.u32.u64 %0, t; }"
        : "=r"(a) : "l"(p));
    return a;
}

__global__ void __launch_bounds__(32) embed_bulk_kernel(
    const int* __restrict__ x,
    const char* __restrict__ weights,
    char* __restrict__ out)
{
    __shared__ __align__(128) char buf[RPC][ROW_BYTES];
    __shared__ __align__(8)  unsigned long long mbar[RPC];

    if (threadIdx.x != 0) return;   // single driver thread

    const int s0 = blockIdx.x * RPC;
    const uint32_t mbar0 = smem_u32(&mbar[0]);
    const uint32_t buf0  = smem_u32(&buf[0][0]);

    // 8 independent index loads in flight first
    int rows[RPC];
#pragma unroll
    for (int i = 0; i < RPC; i++)
        rows[i] = __ldg(&x[s0 + i]);

    // Init mbarriers; one fence orders generic init vs async proxy
#pragma unroll
    for (int i = 0; i < RPC; i++)
        asm volatile("mbarrier.init.shared.b64 [%0], 1;" :: "r"(mbar0 + i * 8) : "memory");
    asm volatile("fence.proxy.async.shared::cta;" ::: "memory");

    // Queue all 8 row loads (24.6 KB in flight per CTA)
#pragma unroll
    for (int i = 0; i < RPC; i++) {
        const uint32_t mb = mbar0 + i * 8;
        asm volatile("mbarrier.arrive.expect_tx.shared.b64 _, [%0], %1;"
                     :: "r"(mb), "r"((uint32_t)ROW_BYTES) : "memory");
        asm volatile(
            "cp.async.bulk.shared::cta.global.mbarrier::complete_tx::bytes "
            "[%0], [%1], %2, [%3];"
            :: "r"(buf0 + i * ROW_BYTES),
               "l"(weights + (size_t)rows[i] * ROW_BYTES),
               "r"((uint32_t)ROW_BYTES),
               "r"(mb)
            : "memory");
    }

    // Drain in order: wait each load, bulk-store the row out.
    // Async->async ordering is provided by the mbarrier wait; no fences needed.
#pragma unroll
    for (int i = 0; i < RPC; i++) {
        const uint32_t mb = mbar0 + i * 8;
        asm volatile(
            "{\n\t"
            ".reg .pred P1;\n\t"
            "WL_%=:\n\t"
            "mbarrier.try_wait.parity.acquire.cta.shared::cta.b64 P1, [%0], 0, 0x989680;\n\t"
            "@P1 bra.uni WD_%=;\n\t"
            "bra.uni WL_%=;\n\t"
            "WD_%=:\n\t"
            "}" :: "r"(mb) : "memory");
        asm volatile(
            "cp.async.bulk.global.shared::cta.bulk_group [%0], [%1], %2;"
            :: "l"(out + (size_t)(s0 + i) * ROW_BYTES),
               "r"(buf0 + i * ROW_BYTES),
               "r"((uint32_t)ROW_BYTES)
            : "memory");
    }
    asm volatile("cp.async.bulk.commit_group;" ::: "memory");
    asm volatile("cp.async.bulk.wait_group 0;" ::: "memory");
}

extern "C" void kernel_launch(void* const* d_in, const int* in_sizes, int n_in,
                              void* d_out, int out_size) {
    const int*  x = (const int*)d_in[0];
    const char* w = (const char*)d_in[1];
    char*       o = (char*)d_out;
    embed_bulk_kernel<<<GRID, 32>>>(x, w, o);
}